// round 1
// baseline (speedup 1.0000x reference)
#include <cuda_runtime.h>
#include <math.h>

#define SEQ 512   // hidden dim of h
#define EMB 512   // embedding dim
#define DD  384   // vfeat channels
#define LL  384   // vfeat regions

// Scratch (device globals — no allocation allowed in kernel_launch)
__device__ float g_gh[EMB];          // wg @ h              (512)
__device__ float g_ts[EMB * LL];     // tanh(s)             (512,384)
__device__ float g_z [LL * LL];      // wh @ tanh(s)        (384,384)
__device__ float g_alpha[LL * LL];   // softmax rows        (384,384)

// ---------------------------------------------------------------------------
// gh[e] = sum_k wg[e,k] * h[k]
// ---------------------------------------------------------------------------
__global__ void k_gh(const float* __restrict__ wg, const float* __restrict__ h) {
    int e = blockIdx.x;
    int t = threadIdx.x;                 // 128 threads
    float p = 0.f;
    for (int k = t; k < SEQ; k += 128)
        p += wg[e * SEQ + k] * h[k];
    #pragma unroll
    for (int o = 16; o; o >>= 1) p += __shfl_down_sync(0xffffffffu, p, o);
    __shared__ float sred[4];
    if ((t & 31) == 0) sred[t >> 5] = p;
    __syncthreads();
    if (t == 0) g_gh[e] = sred[0] + sred[1] + sred[2] + sred[3];
}

// ---------------------------------------------------------------------------
// Register-tiled fp32 GEMM. 64x64 block tile, 16 K-slab, 4x4 per thread,
// 256 threads/block.
//   FIRST=true :  C = tanh( A(512x384)=wv @ B(384x384)=v  + gh[m] ) -> g_ts
//   FIRST=false:  C =       A(384x512)=wh @ g_ts(512x384)           -> g_z
// ---------------------------------------------------------------------------
template <int M, int N, int K, bool FIRST>
__global__ void k_gemm(const float* __restrict__ A, const float* __restrict__ Bin) {
    constexpr int BM = 64, BN = 64, BK = 16;
    __shared__ float As[BK][BM];
    __shared__ float Bs[BK][BN];

    const float* __restrict__ B = FIRST ? Bin : (const float*)g_ts;

    int tx = threadIdx.x;          // 0..255
    int tn = tx & 15;              // 0..15
    int tm = tx >> 4;              // 0..15
    int bm = blockIdx.y;
    int bn = blockIdx.x;

    float acc[4][4] = {};

    for (int k0 = 0; k0 < K; k0 += BK) {
        // Load A tile (BM x BK), store transposed As[k][m]
        #pragma unroll
        for (int t = tx; t < BM * BK; t += 256) {
            int k = t & 15, m = t >> 4;
            As[k][m] = A[(bm * BM + m) * K + k0 + k];
        }
        // Load B tile (BK x BN)
        #pragma unroll
        for (int t = tx; t < BK * BN; t += 256) {
            int n = t & 63, k = t >> 6;
            Bs[k][n] = B[(k0 + k) * N + bn * BN + n];
        }
        __syncthreads();
        #pragma unroll
        for (int k = 0; k < BK; k++) {
            float4 ra = *(const float4*)&As[k][tm * 4];
            float4 rb = *(const float4*)&Bs[k][tn * 4];
            float a_[4] = {ra.x, ra.y, ra.z, ra.w};
            float b_[4] = {rb.x, rb.y, rb.z, rb.w};
            #pragma unroll
            for (int i = 0; i < 4; i++)
                #pragma unroll
                for (int j = 0; j < 4; j++)
                    acc[i][j] += a_[i] * b_[j];
        }
        __syncthreads();
    }

    #pragma unroll
    for (int i = 0; i < 4; i++) {
        int m = bm * BM + tm * 4 + i;
        float bias = FIRST ? g_gh[m] : 0.f;
        #pragma unroll
        for (int j = 0; j < 4; j++) {
            int n = bn * BN + tn * 4 + j;
            float val = acc[i][j] + bias;
            if (FIRST) {
                g_ts[m * N + n] = tanhf(val);
            } else {
                g_z[m * N + n] = val;
            }
        }
    }
}

// ---------------------------------------------------------------------------
// Row softmax over g_z (384 rows x 384 cols) -> g_alpha. 128 threads/row.
// ---------------------------------------------------------------------------
__global__ void k_softmax() {
    int row = blockIdx.x;
    int t = threadIdx.x;                       // 128
    const float* zr = g_z + row * LL;
    float* ar = g_alpha + row * LL;

    float v0 = zr[t], v1 = zr[t + 128], v2 = zr[t + 256];
    float m = fmaxf(v0, fmaxf(v1, v2));

    __shared__ float sred[4];
    #pragma unroll
    for (int o = 16; o; o >>= 1) m = fmaxf(m, __shfl_xor_sync(0xffffffffu, m, o));
    if ((t & 31) == 0) sred[t >> 5] = m;
    __syncthreads();
    float bm = fmaxf(fmaxf(sred[0], sred[1]), fmaxf(sred[2], sred[3]));

    float e0 = __expf(v0 - bm), e1 = __expf(v1 - bm), e2 = __expf(v2 - bm);
    float s = e0 + e1 + e2;
    #pragma unroll
    for (int o = 16; o; o >>= 1) s += __shfl_xor_sync(0xffffffffu, s, o);
    __shared__ float ssum[4];
    if ((t & 31) == 0) ssum[t >> 5] = s;
    __syncthreads();
    float inv = 1.f / (ssum[0] + ssum[1] + ssum[2] + ssum[3]);

    ar[t]       = e0 * inv;
    ar[t + 128] = e1 * inv;
    ar[t + 256] = e2 * inv;
}

// ---------------------------------------------------------------------------
// out[i,j,k] = v[j,k] * alpha[i,j].  float4-vectorized streaming stores.
// total float4 = 384*384*96 = 14,155,776
// ---------------------------------------------------------------------------
__global__ void k_out(const float* __restrict__ v, float4* __restrict__ out) {
    int idx = blockIdx.x * blockDim.x + threadIdx.x;
    // exact grid: no bounds check needed, but keep safe
    const int total = LL * LL * (DD / 4);
    if (idx >= total) return;
    int k4 = idx % 96;
    int j  = (idx / 96) % LL;
    int i  = idx / (96 * LL);
    float a = g_alpha[i * LL + j];
    float4 vv = ((const float4*)v)[j * 96 + k4];
    float4 r;
    r.x = vv.x * a; r.y = vv.y * a; r.z = vv.z * a; r.w = vv.w * a;
    __stcs(&out[idx], r);   // streaming store: output never re-read
}

// ---------------------------------------------------------------------------
extern "C" void kernel_launch(void* const* d_in, const int* in_sizes, int n_in,
                              void* d_out, int out_size) {
    const float* h  = (const float*)d_in[0];   // (512,1)
    const float* v  = (const float*)d_in[1];   // (384,384)
    const float* wh = (const float*)d_in[2];   // (384,512)
    const float* wv = (const float*)d_in[3];   // (512,384)
    const float* wg = (const float*)d_in[4];   // (512,512)
    float* out = (float*)d_out;                // (384,384,384)

    k_gh<<<EMB, 128>>>(wg, h);

    // s = wv@v + gh ; ts = tanh(s)   (M=512, N=384, K=384)
    k_gemm<EMB, LL, DD, true><<<dim3(LL / 64, EMB / 64), 256>>>(wv, v);

    // z = wh @ ts                    (M=384, N=384, K=512)
    k_gemm<LL, LL, EMB, false><<<dim3(LL / 64, LL / 64), 256>>>(wh, nullptr);

    k_softmax<<<LL, 128>>>();

    const int total4 = LL * LL * (DD / 4);
    k_out<<<(total4 + 255) / 256, 256>>>(v, (float4*)d_out);
    (void)in_sizes; (void)n_in; (void)out; (void)out_size;
}

// round 2
// speedup vs baseline: 1.8324x; 1.8324x over previous
#include <cuda_runtime.h>
#include <math.h>

#define SEQ 512   // hidden dim of h
#define EMB 512   // embedding dim
#define DD  384   // vfeat channels
#define LL  384   // vfeat regions

// Scratch (device globals — no allocation allowed in kernel_launch)
__device__ float g_ts[EMB * LL];     // tanh(s)             (512,384)
__device__ float g_z [LL * LL];      // wh @ tanh(s)        (384,384)
__device__ float g_alpha[LL * LL];   // softmax rows        (384,384)

// ---------------------------------------------------------------------------
// Register-tiled fp32 GEMM. 32x32 block tile, BK=32, 2x2 per thread,
// 256 threads/block. High block count -> full SM coverage.
//   FIRST=true :  g_ts = tanh( wv(512x384) @ v(384x384) + (wg@h)[m] )
//                 gh bias computed in-block (fused prologue).
//   FIRST=false:  g_z  = wh(384x512) @ g_ts(512x384)
// ---------------------------------------------------------------------------
template <int M, int N, int K, bool FIRST>
__global__ void __launch_bounds__(256) k_gemm(const float* __restrict__ A,
                                              const float* __restrict__ Bin,
                                              const float* __restrict__ wg,
                                              const float* __restrict__ h) {
    constexpr int BM = 32, BN = 32, BK = 32;
    __shared__ float As[BK][BM + 2];   // +2 pad: keeps float2 aligned, kills 32-way store conflict
    __shared__ float Bs[BK][BN + 2];
    __shared__ float sgh[BM];

    const float* __restrict__ B = FIRST ? Bin : (const float*)g_ts;

    int tx = threadIdx.x;          // 0..255
    int tn = tx & 15;              // 0..15  (n groups of 2)
    int tm = tx >> 4;              // 0..15  (m groups of 2)
    int bm = blockIdx.y;
    int bn = blockIdx.x;

    // Fused bias prologue: sgh[r] = sum_k wg[bm*32+r, k] * h[k]
    if (FIRST) {
        int r = tx >> 3, sub = tx & 7;           // 8 threads per row
        const float* wgr = wg + (bm * BM + r) * SEQ;
        float p = 0.f;
        #pragma unroll 8
        for (int k = sub; k < SEQ; k += 8) p += wgr[k] * h[k];
        p += __shfl_down_sync(0xffffffffu, p, 4);
        p += __shfl_down_sync(0xffffffffu, p, 2);
        p += __shfl_down_sync(0xffffffffu, p, 1);
        if (sub == 0) sgh[r] = p;
    }

    float a00 = 0.f, a01 = 0.f, a10 = 0.f, a11 = 0.f;

    for (int k0 = 0; k0 < K; k0 += BK) {
        __syncthreads();   // also covers sgh on first iteration
        // A tile (BM x BK) -> transposed As[k][m]; global reads coalesced in k
        #pragma unroll
        for (int i = 0; i < 4; i++) {
            int t = tx + i * 256;
            int m = t >> 5, k = t & 31;
            As[k][m] = A[(bm * BM + m) * K + k0 + k];
        }
        // B tile (BK x BN); global reads coalesced in n
        #pragma unroll
        for (int i = 0; i < 4; i++) {
            int t = tx + i * 256;
            int k = t >> 5, n = t & 31;
            Bs[k][n] = B[(k0 + k) * N + bn * BN + n];
        }
        __syncthreads();
        #pragma unroll
        for (int k = 0; k < BK; k++) {
            float2 ra = *(const float2*)&As[k][tm * 2];
            float2 rb = *(const float2*)&Bs[k][tn * 2];
            a00 += ra.x * rb.x; a01 += ra.x * rb.y;
            a10 += ra.y * rb.x; a11 += ra.y * rb.y;
        }
    }

    int m = bm * BM + tm * 2;
    int n = bn * BN + tn * 2;
    if (FIRST) {
        float b0 = sgh[tm * 2], b1 = sgh[tm * 2 + 1];
        g_ts[m * N + n]           = tanhf(a00 + b0);
        g_ts[m * N + n + 1]       = tanhf(a01 + b0);
        g_ts[(m + 1) * N + n]     = tanhf(a10 + b1);
        g_ts[(m + 1) * N + n + 1] = tanhf(a11 + b1);
    } else {
        g_z[m * N + n]           = a00;
        g_z[m * N + n + 1]       = a01;
        g_z[(m + 1) * N + n]     = a10;
        g_z[(m + 1) * N + n + 1] = a11;
    }
}

// ---------------------------------------------------------------------------
// Row softmax: one warp per row, float4 loads, shuffle-only reductions.
// grid = 96 blocks x 128 threads = 384 warps = 384 rows.
// ---------------------------------------------------------------------------
__global__ void k_softmax() {
    int warp = (blockIdx.x * blockDim.x + threadIdx.x) >> 5;   // 0..383
    int lane = threadIdx.x & 31;
    const float4* zr = (const float4*)(g_z + warp * LL);
    float4* ar = (float4*)(g_alpha + warp * LL);

    float4 x0 = zr[lane], x1 = zr[lane + 32], x2 = zr[lane + 64];

    float m = fmaxf(fmaxf(fmaxf(x0.x, x0.y), fmaxf(x0.z, x0.w)),
             fmaxf(fmaxf(fmaxf(x1.x, x1.y), fmaxf(x1.z, x1.w)),
                   fmaxf(fmaxf(x2.x, x2.y), fmaxf(x2.z, x2.w))));
    #pragma unroll
    for (int o = 16; o; o >>= 1) m = fmaxf(m, __shfl_xor_sync(0xffffffffu, m, o));

    x0.x = __expf(x0.x - m); x0.y = __expf(x0.y - m); x0.z = __expf(x0.z - m); x0.w = __expf(x0.w - m);
    x1.x = __expf(x1.x - m); x1.y = __expf(x1.y - m); x1.z = __expf(x1.z - m); x1.w = __expf(x1.w - m);
    x2.x = __expf(x2.x - m); x2.y = __expf(x2.y - m); x2.z = __expf(x2.z - m); x2.w = __expf(x2.w - m);

    float s = (x0.x + x0.y + x0.z + x0.w) + (x1.x + x1.y + x1.z + x1.w)
            + (x2.x + x2.y + x2.z + x2.w);
    #pragma unroll
    for (int o = 16; o; o >>= 1) s += __shfl_xor_sync(0xffffffffu, s, o);
    float inv = 1.f / s;

    x0.x *= inv; x0.y *= inv; x0.z *= inv; x0.w *= inv;
    x1.x *= inv; x1.y *= inv; x1.z *= inv; x1.w *= inv;
    x2.x *= inv; x2.y *= inv; x2.z *= inv; x2.w *= inv;
    ar[lane] = x0; ar[lane + 32] = x1; ar[lane + 64] = x2;
}

// ---------------------------------------------------------------------------
// out[i,j,k] = v[j,k] * alpha[i,j].  float4-vectorized streaming stores.
// total float4 = 384*384*96 = 14,155,776  (226.5 MB written, ~28us HBM floor)
// ---------------------------------------------------------------------------
__global__ void k_out(const float* __restrict__ v, float4* __restrict__ out) {
    int idx = blockIdx.x * blockDim.x + threadIdx.x;
    const int total = LL * LL * (DD / 4);
    if (idx >= total) return;
    int k4 = idx % 96;
    int j  = (idx / 96) % LL;
    int i  = idx / (96 * LL);
    float a = g_alpha[i * LL + j];
    float4 vv = ((const float4*)v)[j * 96 + k4];
    float4 r;
    r.x = vv.x * a; r.y = vv.y * a; r.z = vv.z * a; r.w = vv.w * a;
    __stcs(&out[idx], r);   // streaming store: output never re-read
}

// ---------------------------------------------------------------------------
extern "C" void kernel_launch(void* const* d_in, const int* in_sizes, int n_in,
                              void* d_out, int out_size) {
    const float* h  = (const float*)d_in[0];   // (512,1)
    const float* v  = (const float*)d_in[1];   // (384,384)
    const float* wh = (const float*)d_in[2];   // (384,512)
    const float* wv = (const float*)d_in[3];   // (512,384)
    const float* wg = (const float*)d_in[4];   // (512,512)

    // ts = tanh(wv@v + wg@h)   (M=512, N=384, K=384), 192 blocks
    k_gemm<EMB, LL, DD, true><<<dim3(LL / 32, EMB / 32), 256>>>(wv, v, wg, h);

    // z = wh @ ts              (M=384, N=384, K=512), 144 blocks
    k_gemm<LL, LL, EMB, false><<<dim3(LL / 32, LL / 32), 256>>>(wh, nullptr, nullptr, nullptr);

    k_softmax<<<96, 128>>>();

    const int total4 = LL * LL * (DD / 4);
    k_out<<<(total4 + 255) / 256, 256>>>(v, (float4*)d_out);
    (void)in_sizes; (void)n_in; (void)out_size;
}